// round 2
// baseline (speedup 1.0000x reference)
#include <cuda_runtime.h>
#include <math.h>

#define B_TOT 128
#define NWIN  32
#define NTOK  343
#define HEADS 6
#define HD    32
#define CDIM  192
#define C3    576
#define MTOT  (B_TOT * NTOK)   // 43904

// Scratch (no allocations allowed)
__device__ float g_qkv[MTOT * C3];                         // 101.2 MB
__device__ float g_ao [MTOT * CDIM];                       //  33.7 MB
__device__ float g_bm [NWIN * HEADS * NTOK * NTOK];        //  90.4 MB  bias+mask fused

// ---------------------------------------------------------------------------
// packed f32x2 helpers (FFMA2 — only reachable via PTX)
// ---------------------------------------------------------------------------
__device__ __forceinline__ void ffma2(unsigned long long& d,
                                      unsigned long long a,
                                      unsigned long long b) {
    asm("fma.rn.f32x2 %0, %1, %2, %0;" : "+l"(d) : "l"(a), "l"(b));
}
__device__ __forceinline__ unsigned long long dup2(float x) {
    unsigned long long r;
    asm("mov.b64 %0, {%1, %1};" : "=l"(r) : "f"(x));
    return r;
}
__device__ __forceinline__ float2 unpack2(unsigned long long v) {
    float2 f;
    asm("mov.b64 {%0, %1}, %2;" : "=f"(f.x), "=f"(f.y) : "l"(v));
    return f;
}

// ---------------------------------------------------------------------------
// bm[w][h][i][j] = table[rel[i*N+j]*H + h] + mask[w][i][j]
// ---------------------------------------------------------------------------
__global__ void bm_kernel(const float* __restrict__ table,
                          const int* __restrict__ rel,
                          const float* __restrict__ mask) {
    long long idx = (long long)blockIdx.x * blockDim.x + threadIdx.x;
    const long long total = (long long)NWIN * HEADS * NTOK * NTOK;
    if (idx >= total) return;
    int ij = idx % (NTOK * NTOK);
    int wh = idx / (NTOK * NTOK);
    int h  = wh % HEADS;
    int w  = wh / HEADS;
    g_bm[idx] = table[rel[ij] * HEADS + h] + mask[(size_t)w * NTOK * NTOK + ij];
}

// ---------------------------------------------------------------------------
// C[m][n] = sum_k X[m][k] * W[n][k] + bias[n]       (FFMA2 inner loop)
// M % 64 == 0, N % 64 == 0, K % 16 == 0
// ---------------------------------------------------------------------------
#define GA_STR 68
#define GB_STR 68
__global__ __launch_bounds__(256) void gemm_xwT(const float* __restrict__ X,
                                                const float* __restrict__ W,
                                                const float* __restrict__ bias,
                                                float* __restrict__ C,
                                                int M, int N, int K) {
    __shared__ float sA[16][GA_STR];   // k-major: sA[k][m]
    __shared__ float sB[16][GB_STR];   // k-major: sB[k][n]
    const int m0 = blockIdx.y * 64;
    const int n0 = blockIdx.x * 64;
    const int t  = threadIdx.x;
    const int tr = t / 16, tc = t % 16;

    unsigned long long acc2[4][2];
    #pragma unroll
    for (int i = 0; i < 4; i++) { acc2[i][0] = 0ull; acc2[i][1] = 0ull; }

    for (int k0 = 0; k0 < K; k0 += 16) {
        {   // A tile: thread loads 4 contiguous k, stores transposed
            int idx = t * 4;
            int m = idx / 16, k = idx % 16;
            float4 v = *(const float4*)&X[(size_t)(m0 + m) * K + k0 + k];
            sA[k][m] = v.x; sA[k + 1][m] = v.y; sA[k + 2][m] = v.z; sA[k + 3][m] = v.w;
        }
        {   // B tile: sB[k][n] = W[n0+n][k0+k]
            int idx = t * 4;
            int n = idx / 16, k = idx % 16;
            float4 v = *(const float4*)&W[(size_t)(n0 + n) * K + k0 + k];
            sB[k][n] = v.x; sB[k + 1][n] = v.y; sB[k + 2][n] = v.z; sB[k + 3][n] = v.w;
        }
        __syncthreads();
        #pragma unroll
        for (int k = 0; k < 16; k++) {
            float4 a4 = *(const float4*)&sA[k][tr * 4];
            ulonglong2 b2 = *(const ulonglong2*)&sB[k][tc * 4];
            unsigned long long a0 = dup2(a4.x), a1 = dup2(a4.y),
                               a2 = dup2(a4.z), a3 = dup2(a4.w);
            ffma2(acc2[0][0], a0, b2.x); ffma2(acc2[0][1], a0, b2.y);
            ffma2(acc2[1][0], a1, b2.x); ffma2(acc2[1][1], a1, b2.y);
            ffma2(acc2[2][0], a2, b2.x); ffma2(acc2[2][1], a2, b2.y);
            ffma2(acc2[3][0], a3, b2.x); ffma2(acc2[3][1], a3, b2.y);
        }
        __syncthreads();
    }
    #pragma unroll
    for (int i = 0; i < 4; i++) {
        int m = m0 + tr * 4 + i;
        int n = n0 + tc * 4;
        float2 lo = unpack2(acc2[i][0]);
        float2 hi = unpack2(acc2[i][1]);
        float4 r = make_float4(lo.x + bias[n],     lo.y + bias[n + 1],
                               hi.x + bias[n + 2], hi.y + bias[n + 3]);
        *(float4*)&C[(size_t)m * N + n] = r;
    }
}

// ---------------------------------------------------------------------------
// Attention: one block per (b*H + h, 64-query tile), FFMA2 inner loops
// ---------------------------------------------------------------------------
#define TQ 64
#define TK 64
#define SQ_STR 72          // d-major: sQ[d][q], 32 x 72
#define SK_STR 72          // d-major: sK[d][k], 32 x 72
#define SV_STR 32          // row-major: sV[k][d], 64 x 32
#define SS_STR 344
// floats: 32*72 + 32*72 + 64*32 + 64*344 = 28672 -> 114688 bytes
#define ATTN_SMEM_BYTES ((32*SQ_STR + 32*SK_STR + 64*SV_STR + 64*SS_STR) * 4)

__global__ __launch_bounds__(256, 2) void attn_kernel(const float* __restrict__ qkv,
                                                      float* __restrict__ ao) {
    extern __shared__ float smem[];
    float* sQ = smem;                  // [32][72] d-major
    float* sK = sQ + 32 * SQ_STR;      // [32][72] d-major
    float* sV = sK + 32 * SK_STR;      // [64][32]
    float* sS = sV + 64 * SV_STR;      // [64][344]

    const int bh = blockIdx.y;
    const int b  = bh / HEADS;
    const int h  = bh % HEADS;
    const int q0 = blockIdx.x * TQ;
    const int w  = b % NWIN;
    const int t  = threadIdx.x;
    const float scale = rsqrtf((float)HD);
    const float* bm_base = &g_bm[(size_t)(w * HEADS + h) * NTOK * NTOK];

    // ---- load Q tile (scaled), transposed to d-major ----
    #pragma unroll
    for (int it = 0; it < 2; it++) {
        int idx = (it * 256 + t) * 4;
        int r = idx / HD, d = idx % HD;
        int n = q0 + r;
        float4 v = make_float4(0.f, 0.f, 0.f, 0.f);
        if (n < NTOK)
            v = *(const float4*)&qkv[(size_t)(b * NTOK + n) * C3 + h * HD + d];
        sQ[(d + 0) * SQ_STR + r] = v.x * scale;
        sQ[(d + 1) * SQ_STR + r] = v.y * scale;
        sQ[(d + 2) * SQ_STR + r] = v.z * scale;
        sQ[(d + 3) * SQ_STR + r] = v.w * scale;
    }

    const int tr = t / 16, tc = t % 16;

    // ---- S = QK^T + (bias+mask), tiled over keys ----
    for (int kt = 0; kt < (NTOK + TK - 1) / TK; kt++) {
        const int k0 = kt * TK;
        __syncthreads();
        #pragma unroll
        for (int it = 0; it < 2; it++) {
            int idx = (it * 256 + t) * 4;
            int r = idx / HD, d = idx % HD;
            int n = k0 + r;
            float4 v = make_float4(0.f, 0.f, 0.f, 0.f);
            if (n < NTOK)
                v = *(const float4*)&qkv[(size_t)(b * NTOK + n) * C3 + CDIM + h * HD + d];
            sK[(d + 0) * SK_STR + r] = v.x;
            sK[(d + 1) * SK_STR + r] = v.y;
            sK[(d + 2) * SK_STR + r] = v.z;
            sK[(d + 3) * SK_STR + r] = v.w;
        }
        __syncthreads();

        unsigned long long acc2[4][2];
        #pragma unroll
        for (int i = 0; i < 4; i++) { acc2[i][0] = 0ull; acc2[i][1] = 0ull; }
        #pragma unroll
        for (int d = 0; d < HD; d++) {
            float4 a4 = *(const float4*)&sQ[d * SQ_STR + 4 * tr];
            ulonglong2 b2 = *(const ulonglong2*)&sK[d * SK_STR + 4 * tc];
            unsigned long long a0 = dup2(a4.x), a1 = dup2(a4.y),
                               a2 = dup2(a4.z), a3 = dup2(a4.w);
            ffma2(acc2[0][0], a0, b2.x); ffma2(acc2[0][1], a0, b2.y);
            ffma2(acc2[1][0], a1, b2.x); ffma2(acc2[1][1], a1, b2.y);
            ffma2(acc2[2][0], a2, b2.x); ffma2(acc2[2][1], a2, b2.y);
            ffma2(acc2[3][0], a3, b2.x); ffma2(acc2[3][1], a3, b2.y);
        }
        #pragma unroll
        for (int i = 0; i < 4; i++) {
            int ig = q0 + 4 * tr + i;
            if (ig >= NTOK) continue;
            const float* bm_row = bm_base + (size_t)ig * NTOK;
            float v[4];
            float2 lo = unpack2(acc2[i][0]); float2 hi = unpack2(acc2[i][1]);
            v[0] = lo.x; v[1] = lo.y; v[2] = hi.x; v[3] = hi.y;
            #pragma unroll
            for (int j = 0; j < 4; j++) {
                int jg = k0 + 4 * tc + j;
                if (jg >= NTOK) continue;
                sS[(4 * tr + i) * SS_STR + jg] = v[j] + bm_row[jg];
            }
        }
    }
    __syncthreads();

    // ---- softmax: warp per row (8 warps x 8 rows) ----
    const int warp = t / 32, lane = t % 32;
    for (int rr = 0; rr < 8; rr++) {
        int r = warp * 8 + rr;
        float* row = &sS[r * SS_STR];
        if (q0 + r >= NTOK) {
            for (int j = lane; j < NTOK; j += 32) row[j] = 0.f;
            continue;
        }
        float mx = -1e30f;
        for (int j = lane; j < NTOK; j += 32) mx = fmaxf(mx, row[j]);
        #pragma unroll
        for (int o = 16; o; o >>= 1) mx = fmaxf(mx, __shfl_xor_sync(0xffffffffu, mx, o));
        float sum = 0.f;
        for (int j = lane; j < NTOK; j += 32) {
            float e = __expf(row[j] - mx);
            row[j] = e;
            sum += e;
        }
        #pragma unroll
        for (int o = 16; o; o >>= 1) sum += __shfl_xor_sync(0xffffffffu, sum, o);
        float inv = 1.f / sum;
        for (int j = lane; j < NTOK; j += 32) row[j] *= inv;
    }
    __syncthreads();

    // ---- O = P @ V, tiled over keys (FFMA2) ----
    const int tr2 = t / 8;        // rows {tr2, tr2+32}
    const int tc2 = t % 8;        // dims 4*tc2..+3
    unsigned long long oacc[2][2] = {{0ull, 0ull}, {0ull, 0ull}};
    for (int kt = 0; kt < (NTOK + TK - 1) / TK; kt++) {
        const int k0 = kt * TK;
        #pragma unroll
        for (int it = 0; it < 2; it++) {
            int idx = (it * 256 + t) * 4;
            int r = idx / HD, d = idx % HD;
            int n = k0 + r;
            float4 v = make_float4(0.f, 0.f, 0.f, 0.f);
            if (n < NTOK)
                v = *(const float4*)&qkv[(size_t)(b * NTOK + n) * C3 + 2 * CDIM + h * HD + d];
            *(float4*)&sV[r * SV_STR + d] = v;
        }
        __syncthreads();
        const int kn = (NTOK - k0) < TK ? (NTOK - k0) : TK;
        for (int j = 0; j < kn; j++) {
            unsigned long long p0 = dup2(sS[tr2 * SS_STR + k0 + j]);
            unsigned long long p1 = dup2(sS[(tr2 + 32) * SS_STR + k0 + j]);
            ulonglong2 v2 = *(const ulonglong2*)&sV[j * SV_STR + tc2 * 4];
            ffma2(oacc[0][0], p0, v2.x); ffma2(oacc[0][1], p0, v2.y);
            ffma2(oacc[1][0], p1, v2.x); ffma2(oacc[1][1], p1, v2.y);
        }
        __syncthreads();
    }

    #pragma unroll
    for (int ri = 0; ri < 2; ri++) {
        int n = q0 + tr2 + ri * 32;
        if (n < NTOK) {
            float2 lo = unpack2(oacc[ri][0]);
            float2 hi = unpack2(oacc[ri][1]);
            *(float4*)&ao[(size_t)(b * NTOK + n) * CDIM + h * HD + tc2 * 4] =
                make_float4(lo.x, lo.y, hi.x, hi.y);
        }
    }
}

// ---------------------------------------------------------------------------
extern "C" void kernel_launch(void* const* d_in, const int* in_sizes, int n_in,
                              void* d_out, int out_size) {
    const float* x      = (const float*)d_in[0];
    const float* mask   = (const float*)d_in[1];
    const float* qkv_w  = (const float*)d_in[2];
    const float* qkv_b  = (const float*)d_in[3];
    const float* proj_w = (const float*)d_in[4];
    const float* proj_b = (const float*)d_in[5];
    const float* rpb    = (const float*)d_in[6];
    const int*   rel    = (const int*)d_in[7];
    float* out = (float*)d_out;

    float *p_qkv = nullptr, *p_ao = nullptr;
    cudaGetSymbolAddress((void**)&p_qkv, g_qkv);
    cudaGetSymbolAddress((void**)&p_ao,  g_ao);

    static bool attr_set = false;
    if (!attr_set) {
        cudaFuncSetAttribute(attn_kernel, cudaFuncAttributeMaxDynamicSharedMemorySize,
                             ATTN_SMEM_BYTES);
        attr_set = true;
    }

    // 1) fused bias+mask precompute
    {
        long long total = (long long)NWIN * HEADS * NTOK * NTOK;
        bm_kernel<<<(int)((total + 255) / 256), 256>>>(rpb, rel, mask);
    }
    // 2) QKV GEMM: (43904 x 192) @ (192 x 576)^T
    {
        dim3 grid(C3 / 64, MTOT / 64);
        gemm_xwT<<<grid, 256>>>(x, qkv_w, qkv_b, p_qkv, MTOT, C3, CDIM);
    }
    // 3) attention
    {
        dim3 grid((NTOK + TQ - 1) / TQ, B_TOT * HEADS);
        attn_kernel<<<grid, 256, ATTN_SMEM_BYTES>>>(p_qkv, p_ao);
    }
    // 4) proj GEMM: (43904 x 192) @ (192 x 192)^T
    {
        dim3 grid(CDIM / 64, MTOT / 64);
        gemm_xwT<<<grid, 256>>>(p_ao, proj_w, proj_b, out, MTOT, CDIM, CDIM);
    }
}